// round 1
// baseline (speedup 1.0000x reference)
#include <cuda_runtime.h>

#define EMAX 65536
#define GMAX 64

// Scratch (static __device__ arrays: allocation-free per harness rules)
__device__ float g_x[(size_t)EMAX * 64];
__device__ float g_aggr[(size_t)EMAX * 64];
__device__ float g_deg[EMAX];
__device__ int   g_bt[EMAX];
__device__ float g_gsum[GMAX * 64];
__device__ float g_gcnt[GMAX];

typedef unsigned long long u64;

__device__ __forceinline__ u64 pack2(float x) {
    u64 r; asm("mov.b64 %0, {%1, %2};" : "=l"(r) : "f"(x), "f"(x)); return r;
}
__device__ __forceinline__ void unpack2(u64 v, float& lo, float& hi) {
    asm("mov.b64 {%0, %1}, %2;" : "=f"(lo), "=f"(hi) : "l"(v));
}
__device__ __forceinline__ u64 ffma2(u64 a, u64 b, u64 c) {
    u64 d; asm("fma.rn.f32x2 %0, %1, %2, %3;" : "=l"(d) : "l"(a), "l"(b), "l"(c)); return d;
}
__device__ __forceinline__ float silu_f(float v) { return v / (1.f + __expf(-v)); }

__device__ __forceinline__ void cpys(float* dst, const float* __restrict__ src, int n) {
    const float4* s4 = (const float4*)src; float4* d4 = (float4*)dst;
    for (int i = threadIdx.x; i < (n >> 2); i += blockDim.x) d4[i] = s4[i];
}

// acc[32] = 64 fp32 outputs as packed f32x2 pairs.
// in: 64 contiguous floats (global); ws: 64x64 row-major weight slice in SMEM.
__device__ __forceinline__ void gemv_seg(const float* __restrict__ in, const float* ws,
                                         u64 acc[32], float scale) {
    const float4* in4 = (const float4*)in;
    #pragma unroll 1
    for (int kk = 0; kk < 16; kk++) {
        float4 v = in4[kk];
        u64 vx = pack2(v.x * scale), vy = pack2(v.y * scale);
        u64 vz = pack2(v.z * scale), vw = pack2(v.w * scale);
        const float* wr = ws + kk * 256;
        #pragma unroll
        for (int c = 0; c < 64; c += 4) {
            int i = c >> 1;
            ulonglong2 w0 = *(const ulonglong2*)(wr + c);
            ulonglong2 w1 = *(const ulonglong2*)(wr + 64 + c);
            ulonglong2 w2 = *(const ulonglong2*)(wr + 128 + c);
            ulonglong2 w3 = *(const ulonglong2*)(wr + 192 + c);
            acc[i]   = ffma2(vx, w0.x, acc[i]);   acc[i+1] = ffma2(vx, w0.y, acc[i+1]);
            acc[i]   = ffma2(vy, w1.x, acc[i]);   acc[i+1] = ffma2(vy, w1.y, acc[i+1]);
            acc[i]   = ffma2(vz, w2.x, acc[i]);   acc[i+1] = ffma2(vz, w2.y, acc[i+1]);
            acc[i]   = ffma2(vw, w3.x, acc[i]);   acc[i+1] = ffma2(vw, w3.y, acc[i+1]);
        }
    }
}

// o += silu(acc) @ w2  (64->64). Hidden vector staged through per-thread SMEM strip
// (hst[k*128 + tid]) so the k-loop can index it dynamically without register spills.
__device__ __forceinline__ void gemv2_stage(const u64 acc[32], const float* w2s,
                                            u64 o[32], float* hst) {
    int tid = threadIdx.x;
    #pragma unroll
    for (int C = 0; C < 4; C++) {
        #pragma unroll
        for (int j = 0; j < 8; j++) {
            float lo, hi; unpack2(acc[C * 8 + j], lo, hi);
            hst[(2 * j) * 128 + tid]     = silu_f(lo);
            hst[(2 * j + 1) * 128 + tid] = silu_f(hi);
        }
        const float* w2r = w2s + C * 1024;
        #pragma unroll 1
        for (int k = 0; k < 16; k++) {
            u64 h2 = pack2(hst[k * 128 + tid]);
            const float* wr = w2r + k * 64;
            #pragma unroll
            for (int c = 0; c < 64; c += 4) {
                ulonglong2 w = *(const ulonglong2*)(wr + c);
                o[c >> 1]       = ffma2(h2, w.x, o[c >> 1]);
                o[(c >> 1) + 1] = ffma2(h2, w.y, o[(c >> 1) + 1]);
            }
        }
    }
}

__device__ __forceinline__ void load_bias(const float* bs, u64 a[32]) {
    const ulonglong2* bb = (const ulonglong2*)bs;
    #pragma unroll
    for (int i = 0; i < 16; i++) { ulonglong2 t = bb[i]; a[2 * i] = t.x; a[2 * i + 1] = t.y; }
}

// ---------------- kernels ----------------

__global__ void k_zero_small(int E) {
    int i = blockIdx.x * blockDim.x + threadIdx.x;
    if (i < E) g_deg[i] = 0.f;
    if (i < GMAX * 64) g_gsum[i] = 0.f;
    if (i < GMAX) g_gcnt[i] = 0.f;
}

__global__ void k_zero_aggr(int n) {
    for (int i = blockIdx.x * blockDim.x + threadIdx.x; i < n; i += gridDim.x * blockDim.x)
        g_aggr[i] = 0.f;
}

// bond_init MLP (256->64 silu ->64) + cosine-similarity bond classification
extern "C" __global__ void __launch_bounds__(128, 2)
k_init(const float* __restrict__ af, const int* __restrict__ eidx,
       const float* __restrict__ iw1, const float* __restrict__ ib1,
       const float* __restrict__ iw2, const float* __restrict__ ib2, int E) {
    extern __shared__ float sm[];
    float* w1s = sm;            // 256*64 = 16384
    float* w2s = sm + 16384;    // 4096
    float* b1s = sm + 20480;    // 64
    float* b2s = sm + 20544;    // 64
    float* hst = sm + 20608;    // 2048
    cpys(w1s, iw1, 16384); cpys(w2s, iw2, 4096); cpys(b1s, ib1, 64); cpys(b2s, ib2, 64);
    __syncthreads();
    int e = blockIdx.x * 128 + threadIdx.x;
    if (e >= E) return;
    int r = eidx[e], c = eidx[E + e];
    const float* hi = af + (size_t)r * 128;
    const float* hj = af + (size_t)c * 128;

    // cosine similarity stats
    float dot = 0.f, ni = 0.f, nj = 0.f;
    const float4* a4 = (const float4*)hi;
    const float4* b4 = (const float4*)hj;
    #pragma unroll 4
    for (int i = 0; i < 32; i++) {
        float4 a = a4[i], b = b4[i];
        dot += a.x * b.x + a.y * b.y + a.z * b.z + a.w * b.w;
        ni  += a.x * a.x + a.y * a.y + a.z * a.z + a.w * a.w;
        nj  += b.x * b.x + b.y * b.y + b.z * b.z + b.w * b.w;
    }
    ni = fmaxf(sqrtf(ni), 1e-8f); nj = fmaxf(sqrtf(nj), 1e-8f);
    float sim = dot / (ni * nj);
    int bt = 0;
    if (sim > 0.8f) bt = 1;
    if (sim > 0.9f) bt = 2;
    if (sim < 0.3f) bt = 3;
    g_bt[e] = bt;

    u64 acc[32]; load_bias(b1s, acc);
    gemv_seg(hi,      w1s,          acc, 1.f);
    gemv_seg(hi + 64, w1s + 4096,   acc, 1.f);
    gemv_seg(hj,      w1s + 8192,   acc, 1.f);
    gemv_seg(hj + 64, w1s + 12288,  acc, 1.f);
    u64 o[32]; load_bias(b2s, o);
    gemv2_stage(acc, w2s, o, hst);

    u64* xr = (u64*)(g_x + (size_t)e * 64);
    #pragma unroll
    for (int i = 0; i < 32; i++) xr[i] = o[i];
}

__global__ void k_deg(const int* __restrict__ bei, int BE) {
    int b = blockIdx.x * blockDim.x + threadIdx.x;
    if (b < BE) atomicAdd(&g_deg[bei[BE + b]], 1.f);
}

// message MLP (192->64 silu ->64), scatter-add into aggr[dst]
extern "C" __global__ void __launch_bounds__(128, 3)
k_msg(const int* __restrict__ bei, const float* __restrict__ embl,
      const float* __restrict__ mw1, const float* __restrict__ mb1,
      const float* __restrict__ mw2, const float* __restrict__ mb2, int BE) {
    extern __shared__ float sm[];
    float* w1s = sm;            // 192*64 = 12288
    float* w2s = sm + 12288;    // 4096
    float* b1s = sm + 16384;    // 64
    float* b2s = sm + 16448;    // 64
    float* hst = sm + 16512;    // 2048
    cpys(w1s, mw1, 12288); cpys(w2s, mw2, 4096); cpys(b1s, mb1, 64); cpys(b2s, mb2, 64);
    __syncthreads();
    int b = blockIdx.x * 128 + threadIdx.x;
    if (b >= BE) return;
    int s = bei[b], d = bei[BE + b];
    const float* xd = g_x + (size_t)d * 64;
    const float* xs = g_x + (size_t)s * 64;
    const float* te = embl + g_bt[d] * 64;

    u64 acc[32]; load_bias(b1s, acc);
    gemv_seg(xd, w1s,        acc, 1.f);
    gemv_seg(xs, w1s + 4096, acc, 1.f);
    gemv_seg(te, w1s + 8192, acc, 1.f);
    u64 o[32]; load_bias(b2s, o);
    gemv2_stage(acc, w2s, o, hst);

    float* ag = g_aggr + (size_t)d * 64;
    #pragma unroll
    for (int i = 0; i < 32; i++) {
        float lo, hi; unpack2(o[i], lo, hi);
        asm volatile("red.global.add.v2.f32 [%0], {%1, %2};"
                     :: "l"(ag + 2 * i), "f"(lo), "f"(hi) : "memory");
    }
}

// update MLP (128->64 silu ->64), residual into x
extern "C" __global__ void __launch_bounds__(128, 3)
k_upd(const float* __restrict__ uw1, const float* __restrict__ ub1,
      const float* __restrict__ uw2, const float* __restrict__ ub2, int E) {
    extern __shared__ float sm[];
    float* w1s = sm;            // 128*64 = 8192
    float* w2s = sm + 8192;     // 4096
    float* b1s = sm + 12288;    // 64
    float* b2s = sm + 12352;    // 64
    float* hst = sm + 12416;    // 2048
    cpys(w1s, uw1, 8192); cpys(w2s, uw2, 4096); cpys(b1s, ub1, 64); cpys(b2s, ub2, 64);
    __syncthreads();
    int e = blockIdx.x * 128 + threadIdx.x;
    if (e >= E) return;
    float rdiv = 1.f / fmaxf(g_deg[e], 1.f);

    u64 acc[32]; load_bias(b1s, acc);
    gemv_seg(g_aggr + (size_t)e * 64, w1s,        acc, rdiv);
    gemv_seg(g_x    + (size_t)e * 64, w1s + 4096, acc, 1.f);
    u64 o[32]; load_bias(b2s, o);
    gemv2_stage(acc, w2s, o, hst);

    float4* x4 = (float4*)(g_x + (size_t)e * 64);
    #pragma unroll
    for (int i = 0; i < 16; i++) {
        float4 xv = x4[i];
        float a, b; unpack2(o[2 * i], a, b);
        float c, d; unpack2(o[2 * i + 1], c, d);
        xv.x += a; xv.y += b; xv.z += c; xv.w += d;
        x4[i] = xv;
    }
}

__global__ void k_cnt(const int* __restrict__ eidx, const int* __restrict__ batch, int E) {
    int e = blockIdx.x * blockDim.x + threadIdx.x;
    if (e < E) atomicAdd(&g_gcnt[batch[eidx[e]]], 1.f);
}

// graph pooling: edges are sorted by graph -> run-length flush minimizes atomics
__global__ void k_pool(const int* __restrict__ eidx, const int* __restrict__ batch, int E) {
    int t = threadIdx.x;  // 64 threads, one column each
    int e0 = blockIdx.x * 512;
    if (e0 >= E) return;
    int e1 = min(e0 + 512, E);
    int curg = batch[eidx[e0]];
    float sum = 0.f;
    for (int e = e0; e < e1; e++) {
        int g = batch[eidx[e]];
        if (g != curg) { atomicAdd(&g_gsum[curg * 64 + t], sum); sum = 0.f; curg = g; }
        sum += g_x[(size_t)e * 64 + t];
    }
    atomicAdd(&g_gsum[curg * 64 + t], sum);
}

__global__ void k_fin(float* __restrict__ out, int G) {
    int i = blockIdx.x * blockDim.x + threadIdx.x;
    if (i < G * 64) out[i] = g_gsum[i] / fmaxf(g_gcnt[i >> 6], 1.f);
}

__global__ void k_copy(float4* __restrict__ out, int n4) {
    const float4* src = (const float4*)g_x;
    for (int i = blockIdx.x * blockDim.x + threadIdx.x; i < n4; i += gridDim.x * blockDim.x)
        out[i] = src[i];
}

// ---------------- host launcher ----------------

extern "C" void kernel_launch(void* const* d_in, const int* in_sizes, int n_in,
                              void* d_out, int out_size) {
    const float* af    = (const float*)d_in[0];
    const int*   batch = (const int*)d_in[3];
    const int*   eidx  = (const int*)d_in[4];
    const int*   bei   = (const int*)d_in[5];
    const float* iw1 = (const float*)d_in[6];
    const float* ib1 = (const float*)d_in[7];
    const float* iw2 = (const float*)d_in[8];
    const float* ib2 = (const float*)d_in[9];
    const float* emb = (const float*)d_in[10];
    const float* mw1 = (const float*)d_in[11];
    const float* mb1 = (const float*)d_in[12];
    const float* mw2 = (const float*)d_in[13];
    const float* mb2 = (const float*)d_in[14];
    const float* uw1 = (const float*)d_in[15];
    const float* ub1 = (const float*)d_in[16];
    const float* uw2 = (const float*)d_in[17];
    const float* ub2 = (const float*)d_in[18];

    int E  = in_sizes[4] / 2;
    int BE = in_sizes[5] / 2;
    int G  = out_size / 64 - E;

    const int SH_INIT = (16384 + 4096 + 64 + 64 + 2048) * 4;  // 90624
    const int SH_MSG  = (12288 + 4096 + 64 + 64 + 2048) * 4;  // 74240
    const int SH_UPD  = ( 8192 + 4096 + 64 + 64 + 2048) * 4;  // 57856
    cudaFuncSetAttribute(k_init, cudaFuncAttributeMaxDynamicSharedMemorySize, SH_INIT);
    cudaFuncSetAttribute(k_msg,  cudaFuncAttributeMaxDynamicSharedMemorySize, SH_MSG);
    cudaFuncSetAttribute(k_upd,  cudaFuncAttributeMaxDynamicSharedMemorySize, SH_UPD);

    int gE128  = (E + 127) / 128;
    int gBE128 = (BE + 127) / 128;
    int gE256  = (E + 255) / 256;
    int gBE256 = (BE + 255) / 256;

    k_zero_small<<<gE256, 256>>>(E);
    k_init<<<gE128, 128, SH_INIT>>>(af, eidx, iw1, ib1, iw2, ib2, E);
    k_deg<<<gBE256, 256>>>(bei, BE);

    for (int l = 0; l < 2; l++) {
        k_zero_aggr<<<1024, 256>>>(E * 64);
        k_msg<<<gBE128, 128, SH_MSG>>>(bei, emb + l * 320,
                                       mw1 + l * 12288, mb1 + l * 64,
                                       mw2 + l * 4096,  mb2 + l * 64, BE);
        k_upd<<<gE128, 128, SH_UPD>>>(uw1 + l * 8192, ub1 + l * 64,
                                      uw2 + l * 4096, ub2 + l * 64, E);
    }

    k_cnt<<<gE256, 256>>>(eidx, batch, E);
    k_pool<<<(E + 511) / 512, 64>>>(eidx, batch, E);
    k_fin<<<(G * 64 + 255) / 256, 256>>>((float*)d_out + (size_t)E * 64, G);
    k_copy<<<1024, 256>>>((float4*)d_out, E * 16);
}

// round 2
// speedup vs baseline: 1.2306x; 1.2306x over previous
#include <cuda_runtime.h>

#define EMAX 65536
#define GMAX 64

__device__ float g_x[(size_t)EMAX * 64];
__device__ float g_aggr[(size_t)EMAX * 64];
__device__ float g_deg[EMAX];
__device__ int   g_bt[EMAX];
__device__ float g_gsum[GMAX * 64];
__device__ float g_gcnt[GMAX];

typedef unsigned long long u64;

__device__ __forceinline__ u64 pack2(float x) {
    u64 r; asm("mov.b64 %0, {%1, %2};" : "=l"(r) : "f"(x), "f"(x)); return r;
}
__device__ __forceinline__ void unpack2(u64 v, float& lo, float& hi) {
    asm("mov.b64 {%0, %1}, %2;" : "=f"(lo), "=f"(hi) : "l"(v));
}
__device__ __forceinline__ float gethalf(u64 v, int which) {
    float lo, hi; unpack2(v, lo, hi); return which ? hi : lo;
}
__device__ __forceinline__ u64 ffma2(u64 a, u64 b, u64 c) {
    u64 d; asm("fma.rn.f32x2 %0, %1, %2, %3;" : "=l"(d) : "l"(a), "l"(b), "l"(c)); return d;
}
__device__ __forceinline__ float silu_f(float v) {
    return __fdividef(v, 1.f + __expf(-v));
}

// Copy [K][64] row-major weights into swizzled SMEM: row stride 80 floats,
// quarter q of each row at offset 20*q (bank offsets 0/20/8/28 -> conflict-free).
__device__ __forceinline__ void copy_sw(float* dst, const float* __restrict__ src, int K) {
    for (int i = threadIdx.x; i < K * 64; i += blockDim.x) {
        int k = i >> 6, c = i & 63;
        dst[k * 80 + (c >> 4) * 20 + (c & 15)] = src[i];
    }
}

// Quad GEMV segment: 64 inputs -> own 16-col quarter, 4 edges per thread.
// wq already offset by q*20. a[e][8] = 16 cols as f32x2 pairs.
template<bool SCALED>
__device__ __forceinline__ void gemv_seg4(
    const float* __restrict__ i0, const float* __restrict__ i1,
    const float* __restrict__ i2, const float* __restrict__ i3,
    const float* wq, u64 a[4][8],
    float s0 = 1.f, float s1 = 1.f, float s2 = 1.f, float s3 = 1.f)
{
    const float4* p0 = (const float4*)i0;
    const float4* p1 = (const float4*)i1;
    const float4* p2 = (const float4*)i2;
    const float4* p3 = (const float4*)i3;
    #pragma unroll 1
    for (int kk = 0; kk < 16; kk++) {
        float4 v0 = p0[kk], v1 = p1[kk], v2 = p2[kk], v3 = p3[kk];
        if (SCALED) {
            v0.x *= s0; v0.y *= s0; v0.z *= s0; v0.w *= s0;
            v1.x *= s1; v1.y *= s1; v1.z *= s1; v1.w *= s1;
            v2.x *= s2; v2.y *= s2; v2.z *= s2; v2.w *= s2;
            v3.x *= s3; v3.y *= s3; v3.z *= s3; v3.w *= s3;
        }
        const float* wr = wq + kk * 320;
        #pragma unroll
        for (int j = 0; j < 4; j++) {
            float f0 = (j == 0) ? v0.x : (j == 1) ? v0.y : (j == 2) ? v0.z : v0.w;
            float f1 = (j == 0) ? v1.x : (j == 1) ? v1.y : (j == 2) ? v1.z : v1.w;
            float f2 = (j == 0) ? v2.x : (j == 1) ? v2.y : (j == 2) ? v2.z : v2.w;
            float f3 = (j == 0) ? v3.x : (j == 1) ? v3.y : (j == 2) ? v3.z : v3.w;
            u64 q0 = pack2(f0), q1 = pack2(f1), q2 = pack2(f2), q3 = pack2(f3);
            const float* w = wr + j * 80;
            #pragma unroll
            for (int cc = 0; cc < 4; cc++) {
                ulonglong2 wv = *(const ulonglong2*)(w + cc * 4);
                a[0][2*cc]   = ffma2(q0, wv.x, a[0][2*cc]);
                a[0][2*cc+1] = ffma2(q0, wv.y, a[0][2*cc+1]);
                a[1][2*cc]   = ffma2(q1, wv.x, a[1][2*cc]);
                a[1][2*cc+1] = ffma2(q1, wv.y, a[1][2*cc+1]);
                a[2][2*cc]   = ffma2(q2, wv.x, a[2][2*cc]);
                a[2][2*cc+1] = ffma2(q2, wv.y, a[2][2*cc+1]);
                a[3][2*cc]   = ffma2(q3, wv.x, a[3][2*cc]);
                a[3][2*cc+1] = ffma2(q3, wv.y, a[3][2*cc+1]);
            }
        }
    }
}

// Second GEMV (64->own 16 cols, 4 edges) with chunked SMEM hidden exchange.
// hst: CK rows x 128 floats. w2q already offset by q*20.
template<int CK>
__device__ __forceinline__ void gemv2_q(const u64 a[4][8], const float* w2q,
                                        u64 o[4][8], float* hst, int q, int g)
{
    #pragma unroll
    for (int C = 0; C < 64 / CK; C++) {
        if (q == (C * CK) >> 4) {
            #pragma unroll
            for (int kl = 0; kl < CK; kl++) {
                int lk = (C * CK) % 16 + kl;   // compile-time
                int j = lk >> 1, h = lk & 1;
                float4 sv;
                sv.x = silu_f(gethalf(a[0][j], h));
                sv.y = silu_f(gethalf(a[1][j], h));
                sv.z = silu_f(gethalf(a[2][j], h));
                sv.w = silu_f(gethalf(a[3][j], h));
                *(float4*)(hst + kl * 128 + 4 * g) = sv;
            }
        }
        __syncthreads();
        const float* wr = w2q + (C * CK) * 80;
        #pragma unroll 1
        for (int kl = 0; kl < CK; kl++) {
            float4 hv = *(const float4*)(hst + kl * 128 + 4 * g);
            u64 h0 = pack2(hv.x), h1 = pack2(hv.y), h2 = pack2(hv.z), h3 = pack2(hv.w);
            const float* w = wr + kl * 80;
            #pragma unroll
            for (int cc = 0; cc < 4; cc++) {
                ulonglong2 wv = *(const ulonglong2*)(w + cc * 4);
                o[0][2*cc]   = ffma2(h0, wv.x, o[0][2*cc]);
                o[0][2*cc+1] = ffma2(h0, wv.y, o[0][2*cc+1]);
                o[1][2*cc]   = ffma2(h1, wv.x, o[1][2*cc]);
                o[1][2*cc+1] = ffma2(h1, wv.y, o[1][2*cc+1]);
                o[2][2*cc]   = ffma2(h2, wv.x, o[2][2*cc]);
                o[2][2*cc+1] = ffma2(h2, wv.y, o[2][2*cc+1]);
                o[3][2*cc]   = ffma2(h3, wv.x, o[3][2*cc]);
                o[3][2*cc+1] = ffma2(h3, wv.y, o[3][2*cc+1]);
            }
        }
        __syncthreads();
    }
}

__device__ __forceinline__ void load_bias_q(const float* bs, int q, u64 a[4][8]) {
    const ulonglong2* bb = (const ulonglong2*)(bs + 16 * q);
    #pragma unroll
    for (int cc = 0; cc < 4; cc++) {
        ulonglong2 t = bb[cc];
        #pragma unroll
        for (int e = 0; e < 4; e++) { a[e][2*cc] = t.x; a[e][2*cc+1] = t.y; }
    }
}

// ---------------- kernels ----------------

__global__ void k_zero_small(int E) {
    int i = blockIdx.x * blockDim.x + threadIdx.x;
    if (i < E) g_deg[i] = 0.f;
    if (i < GMAX * 64) g_gsum[i] = 0.f;
    if (i < GMAX) g_gcnt[i] = 0.f;
}

__global__ void k_zero_aggr(int n) {
    for (int i = blockIdx.x * blockDim.x + threadIdx.x; i < n; i += gridDim.x * blockDim.x)
        g_aggr[i] = 0.f;
}

extern "C" __global__ void __launch_bounds__(128, 2)
k_init(const float* __restrict__ af, const int* __restrict__ eidx,
       const float* __restrict__ iw1, const float* __restrict__ ib1,
       const float* __restrict__ iw2, const float* __restrict__ ib2, int E) {
    extern __shared__ float sm[];
    float* w1s = sm;                // 256*80 = 20480
    float* w2s = sm + 20480;        // 5120
    float* b1s = sm + 25600;        // 64
    float* b2s = sm + 25664;        // 64
    float* hst = sm + 25728;        // 8*128 = 1024
    copy_sw(w1s, iw1, 256); copy_sw(w2s, iw2, 64);
    if (threadIdx.x < 64) { b1s[threadIdx.x] = ib1[threadIdx.x]; b2s[threadIdx.x] = ib2[threadIdx.x]; }
    __syncthreads();

    int tid = threadIdx.x, q = tid & 3, g = tid >> 2;
    int ebase = blockIdx.x * 128 + 4 * g;
    bool val[4]; const float *hi[4], *hj[4];
    #pragma unroll
    for (int j = 0; j < 4; j++) {
        int e = ebase + j; val[j] = e < E; int ec = val[j] ? e : 0;
        int r = eidx[ec], c = eidx[E + ec];
        hi[j] = af + (size_t)r * 128; hj[j] = af + (size_t)c * 128;
    }

    // cosine similarity: quad-split over dims [32q, 32q+32), shuffle-reduce
    float dot[4], ni[4], nj[4];
    #pragma unroll
    for (int j = 0; j < 4; j++) {
        dot[j] = 0.f; ni[j] = 0.f; nj[j] = 0.f;
        const float4* A = (const float4*)hi[j] + 8 * q;
        const float4* B = (const float4*)hj[j] + 8 * q;
        #pragma unroll
        for (int t = 0; t < 8; t++) {
            float4 a = A[t], b = B[t];
            dot[j] += a.x*b.x + a.y*b.y + a.z*b.z + a.w*b.w;
            ni[j]  += a.x*a.x + a.y*a.y + a.z*a.z + a.w*a.w;
            nj[j]  += b.x*b.x + b.y*b.y + b.z*b.z + b.w*b.w;
        }
    }
    #pragma unroll
    for (int j = 0; j < 4; j++) {
        dot[j] += __shfl_xor_sync(~0u, dot[j], 1); dot[j] += __shfl_xor_sync(~0u, dot[j], 2);
        ni[j]  += __shfl_xor_sync(~0u, ni[j], 1);  ni[j]  += __shfl_xor_sync(~0u, ni[j], 2);
        nj[j]  += __shfl_xor_sync(~0u, nj[j], 1);  nj[j]  += __shfl_xor_sync(~0u, nj[j], 2);
    }
    if (q == 0) {
        #pragma unroll
        for (int j = 0; j < 4; j++) {
            if (val[j]) {
                float a = fmaxf(sqrtf(ni[j]), 1e-8f), b = fmaxf(sqrtf(nj[j]), 1e-8f);
                float sim = dot[j] / (a * b);
                int bt = 0;
                if (sim > 0.8f) bt = 1;
                if (sim > 0.9f) bt = 2;
                if (sim < 0.3f) bt = 3;
                g_bt[ebase + j] = bt;
            }
        }
    }

    const float* wq = w1s + q * 20;
    u64 a[4][8]; load_bias_q(b1s, q, a);
    gemv_seg4<false>(hi[0],      hi[1],      hi[2],      hi[3],      wq,            a);
    gemv_seg4<false>(hi[0] + 64, hi[1] + 64, hi[2] + 64, hi[3] + 64, wq + 64 * 80,  a);
    gemv_seg4<false>(hj[0],      hj[1],      hj[2],      hj[3],      wq + 128 * 80, a);
    gemv_seg4<false>(hj[0] + 64, hj[1] + 64, hj[2] + 64, hj[3] + 64, wq + 192 * 80, a);
    u64 o[4][8]; load_bias_q(b2s, q, o);
    gemv2_q<8>(a, w2s + q * 20, o, hst, q, g);

    #pragma unroll
    for (int e = 0; e < 4; e++) {
        if (!val[e]) continue;
        ulonglong2* xp = (ulonglong2*)(g_x + (size_t)(ebase + e) * 64 + 16 * q);
        #pragma unroll
        for (int cc = 0; cc < 4; cc++) {
            ulonglong2 t; t.x = o[e][2*cc]; t.y = o[e][2*cc+1]; xp[cc] = t;
        }
    }
}

__global__ void k_deg(const int* __restrict__ bei, int BE) {
    int b = blockIdx.x * blockDim.x + threadIdx.x;
    if (b < BE) atomicAdd(&g_deg[bei[BE + b]], 1.f);
}

extern "C" __global__ void __launch_bounds__(128, 2)
k_msg(const int* __restrict__ bei, const float* __restrict__ embl,
      const float* __restrict__ mw1, const float* __restrict__ mb1,
      const float* __restrict__ mw2, const float* __restrict__ mb2, int BE) {
    extern __shared__ float sm[];
    float* w1s = sm;                // 192*80 = 15360
    float* w2s = sm + 15360;        // 5120
    float* b1s = sm + 20480;        // 64
    float* b2s = sm + 20544;        // 64
    float* hst = sm + 20608;        // 1024
    copy_sw(w1s, mw1, 192); copy_sw(w2s, mw2, 64);
    if (threadIdx.x < 64) { b1s[threadIdx.x] = mb1[threadIdx.x]; b2s[threadIdx.x] = mb2[threadIdx.x]; }
    __syncthreads();

    int tid = threadIdx.x, q = tid & 3, g = tid >> 2;
    int ebase = blockIdx.x * 128 + 4 * g;
    bool val[4]; int d_[4];
    const float *xd[4], *xs[4], *te[4];
    #pragma unroll
    for (int j = 0; j < 4; j++) {
        int e = ebase + j; val[j] = e < BE; int ec = val[j] ? e : 0;
        int s = bei[ec]; int d = bei[BE + ec]; d_[j] = d;
        xd[j] = g_x + (size_t)d * 64;
        xs[j] = g_x + (size_t)s * 64;
        te[j] = embl + g_bt[d] * 64;
    }

    const float* wq = w1s + q * 20;
    u64 a[4][8]; load_bias_q(b1s, q, a);
    gemv_seg4<false>(xd[0], xd[1], xd[2], xd[3], wq,            a);
    gemv_seg4<false>(xs[0], xs[1], xs[2], xs[3], wq + 64 * 80,  a);
    gemv_seg4<false>(te[0], te[1], te[2], te[3], wq + 128 * 80, a);
    u64 o[4][8]; load_bias_q(b2s, q, o);
    gemv2_q<8>(a, w2s + q * 20, o, hst, q, g);

    #pragma unroll
    for (int e = 0; e < 4; e++) {
        if (!val[e]) continue;
        float* ag = g_aggr + (size_t)d_[e] * 64 + 16 * q;
        #pragma unroll
        for (int cc = 0; cc < 4; cc++) {
            float x0, x1, x2, x3;
            unpack2(o[e][2*cc], x0, x1); unpack2(o[e][2*cc+1], x2, x3);
            asm volatile("red.global.add.v4.f32 [%0], {%1,%2,%3,%4};"
                         :: "l"(ag + 4 * cc), "f"(x0), "f"(x1), "f"(x2), "f"(x3) : "memory");
        }
    }
}

extern "C" __global__ void __launch_bounds__(128, 2)
k_upd(const float* __restrict__ uw1, const float* __restrict__ ub1,
      const float* __restrict__ uw2, const float* __restrict__ ub2, int E) {
    extern __shared__ float sm[];
    float* w1s = sm;                // 128*80 = 10240
    float* w2s = sm + 10240;        // 5120
    float* b1s = sm + 15360;        // 64
    float* b2s = sm + 15424;        // 64
    float* hst = sm + 15488;        // 1024
    copy_sw(w1s, uw1, 128); copy_sw(w2s, uw2, 64);
    if (threadIdx.x < 64) { b1s[threadIdx.x] = ub1[threadIdx.x]; b2s[threadIdx.x] = ub2[threadIdx.x]; }
    __syncthreads();

    int tid = threadIdx.x, q = tid & 3, g = tid >> 2;
    int ebase = blockIdx.x * 128 + 4 * g;
    bool val[4]; int ec[4]; float rdiv[4];
    #pragma unroll
    for (int j = 0; j < 4; j++) {
        int e = ebase + j; val[j] = e < E; ec[j] = val[j] ? e : 0;
        rdiv[j] = 1.f / fmaxf(g_deg[ec[j]], 1.f);
    }

    const float* wq = w1s + q * 20;
    u64 a[4][8]; load_bias_q(b1s, q, a);
    gemv_seg4<true>(g_aggr + (size_t)ec[0] * 64, g_aggr + (size_t)ec[1] * 64,
                    g_aggr + (size_t)ec[2] * 64, g_aggr + (size_t)ec[3] * 64,
                    wq, a, rdiv[0], rdiv[1], rdiv[2], rdiv[3]);
    gemv_seg4<false>(g_x + (size_t)ec[0] * 64, g_x + (size_t)ec[1] * 64,
                     g_x + (size_t)ec[2] * 64, g_x + (size_t)ec[3] * 64,
                     wq + 64 * 80, a);
    u64 o[4][8]; load_bias_q(b2s, q, o);
    gemv2_q<8>(a, w2s + q * 20, o, hst, q, g);

    #pragma unroll
    for (int e = 0; e < 4; e++) {
        if (!val[e]) continue;
        float4* xp = (float4*)(g_x + (size_t)ec[e] * 64 + 16 * q);
        #pragma unroll
        for (int cc = 0; cc < 4; cc++) {
            float4 xv = xp[cc];
            float a0, a1, a2, a3;
            unpack2(o[e][2*cc], a0, a1); unpack2(o[e][2*cc+1], a2, a3);
            xv.x += a0; xv.y += a1; xv.z += a2; xv.w += a3;
            xp[cc] = xv;
        }
    }
}

__global__ void k_cnt(const int* __restrict__ eidx, const int* __restrict__ batch, int E) {
    int e = blockIdx.x * blockDim.x + threadIdx.x;
    if (e < E) atomicAdd(&g_gcnt[batch[eidx[e]]], 1.f);
}

__global__ void k_pool2(const int* __restrict__ eidx, const int* __restrict__ batch, int E) {
    int i = blockIdx.x * blockDim.x + threadIdx.x;
    if (i >= E * 16) return;
    int e = i >> 4, cc = i & 15;
    int gph = batch[eidx[e]];
    float4 v = ((const float4*)g_x)[(size_t)e * 16 + cc];
    float* dst = g_gsum + gph * 64 + cc * 4;
    asm volatile("red.global.add.v4.f32 [%0], {%1,%2,%3,%4};"
                 :: "l"(dst), "f"(v.x), "f"(v.y), "f"(v.z), "f"(v.w) : "memory");
}

__global__ void k_fin(float* __restrict__ out, int G) {
    int i = blockIdx.x * blockDim.x + threadIdx.x;
    if (i < G * 64) out[i] = g_gsum[i] / fmaxf(g_gcnt[i >> 6], 1.f);
}

__global__ void k_copy(float4* __restrict__ out, int n4) {
    const float4* src = (const float4*)g_x;
    for (int i = blockIdx.x * blockDim.x + threadIdx.x; i < n4; i += gridDim.x * blockDim.x)
        out[i] = src[i];
}

// ---------------- host launcher ----------------

extern "C" void kernel_launch(void* const* d_in, const int* in_sizes, int n_in,
                              void* d_out, int out_size) {
    const float* af    = (const float*)d_in[0];
    const int*   batch = (const int*)d_in[3];
    const int*   eidx  = (const int*)d_in[4];
    const int*   bei   = (const int*)d_in[5];
    const float* iw1 = (const float*)d_in[6];
    const float* ib1 = (const float*)d_in[7];
    const float* iw2 = (const float*)d_in[8];
    const float* ib2 = (const float*)d_in[9];
    const float* emb = (const float*)d_in[10];
    const float* mw1 = (const float*)d_in[11];
    const float* mb1 = (const float*)d_in[12];
    const float* mw2 = (const float*)d_in[13];
    const float* mb2 = (const float*)d_in[14];
    const float* uw1 = (const float*)d_in[15];
    const float* ub1 = (const float*)d_in[16];
    const float* uw2 = (const float*)d_in[17];
    const float* ub2 = (const float*)d_in[18];

    int E  = in_sizes[4] / 2;
    int BE = in_sizes[5] / 2;
    int G  = out_size / 64 - E;

    const int SH_INIT = 26752 * 4;   // 107008 B
    const int SH_MSG  = 21632 * 4;   // 86528 B
    const int SH_UPD  = 16512 * 4;   // 66048 B
    cudaFuncSetAttribute(k_init, cudaFuncAttributeMaxDynamicSharedMemorySize, SH_INIT);
    cudaFuncSetAttribute(k_msg,  cudaFuncAttributeMaxDynamicSharedMemorySize, SH_MSG);
    cudaFuncSetAttribute(k_upd,  cudaFuncAttributeMaxDynamicSharedMemorySize, SH_UPD);

    int gE128  = (E + 127) / 128;
    int gBE128 = (BE + 127) / 128;
    int gE256  = (E + 255) / 256;
    int gBE256 = (BE + 255) / 256;

    k_zero_small<<<gE256, 256>>>(E);
    k_init<<<gE128, 128, SH_INIT>>>(af, eidx, iw1, ib1, iw2, ib2, E);
    k_deg<<<gBE256, 256>>>(bei, BE);

    for (int l = 0; l < 2; l++) {
        k_zero_aggr<<<1024, 256>>>(E * 64);
        k_msg<<<gBE128, 128, SH_MSG>>>(bei, emb + l * 320,
                                       mw1 + l * 12288, mb1 + l * 64,
                                       mw2 + l * 4096,  mb2 + l * 64, BE);
        k_upd<<<gE128, 128, SH_UPD>>>(uw1 + l * 8192, ub1 + l * 64,
                                      uw2 + l * 4096, ub2 + l * 64, E);
    }

    k_cnt<<<gE256, 256>>>(eidx, batch, E);
    k_pool2<<<(E * 16 + 255) / 256, 256>>>(eidx, batch, E);
    k_fin<<<(G * 64 + 255) / 256, 256>>>((float*)d_out + (size_t)E * 64, G);
    k_copy<<<1024, 256>>>((float4*)d_out, E * 16);
}